// round 7
// baseline (speedup 1.0000x reference)
#include <cuda_runtime.h>
#include <cstdint>
#include <math.h>

#define N_B 64
#define T_T 512
#define D_D 512
#define H_H 512

// 67 MB scratch for xWx (device global: allocation-free per harness rules)
__device__ float g_xwx[(size_t)N_B * T_T * H_H];

// ---- packed fp32x2 helpers (Blackwell FFMA2 path) ----
__device__ __forceinline__ unsigned long long ffma2(
    unsigned long long a, unsigned long long b, unsigned long long c) {
    unsigned long long d;
    asm("fma.rn.f32x2 %0, %1, %2, %3;" : "=l"(d) : "l"(a), "l"(b), "l"(c));
    return d;
}
__device__ __forceinline__ unsigned long long fadd2(
    unsigned long long a, unsigned long long b) {
    unsigned long long d;
    asm("add.rn.f32x2 %0, %1, %2;" : "=l"(d) : "l"(a), "l"(b));
    return d;
}
__device__ __forceinline__ unsigned long long pack2(float lo, float hi) {
    unsigned long long r;
    asm("mov.b64 %0, {%1, %2};" : "=l"(r) : "f"(lo), "f"(hi));
    return r;
}

// ---------------------------------------------------------------------------
// Phase 1: g_xwx[m][h] = x[m][:] @ Wx[:][h] + b[h]  (32768 x 512 SGEMM)
// ---------------------------------------------------------------------------
#define BM 128
#define BN 128
#define BK 16

__global__ __launch_bounds__(256, 2) void xwx_gemm_kernel(
    const float* __restrict__ A,
    const float* __restrict__ B,
    const float* __restrict__ bias)
{
    __shared__ float As[BK][BM + 4];
    __shared__ float Bs[BK][BN + 4];

    const int tid = threadIdx.x;
    const int bm = blockIdx.y * BM;
    const int bn = blockIdx.x * BN;

    const int ty = tid >> 4;
    const int tx = tid & 15;

    const int aRow = tid >> 2;
    const int aCol = (tid & 3) << 2;
    const int bRow = tid >> 5;
    const int bCol = (tid & 31) << 2;

    unsigned long long acc2[8][4];
#pragma unroll
    for (int i = 0; i < 8; i++)
#pragma unroll
        for (int j = 0; j < 4; j++) acc2[i][j] = 0ull;

    for (int kt = 0; kt < D_D; kt += BK) {
#pragma unroll
        for (int rr = 0; rr < BM; rr += 64) {
            float4 a = *(const float4*)&A[(size_t)(bm + aRow + rr) * D_D + kt + aCol];
            As[aCol + 0][aRow + rr] = a.x;
            As[aCol + 1][aRow + rr] = a.y;
            As[aCol + 2][aRow + rr] = a.z;
            As[aCol + 3][aRow + rr] = a.w;
        }
#pragma unroll
        for (int rr = 0; rr < BK; rr += 8) {
            float4 b4 = *(const float4*)&B[(size_t)(kt + bRow + rr) * H_H + bn + bCol];
            *(float4*)&Bs[bRow + rr][bCol] = b4;
        }
        __syncthreads();

#pragma unroll
        for (int k = 0; k < BK; k++) {
            float4 a0 = *(const float4*)&As[k][ty * 4];
            float4 a1 = *(const float4*)&As[k][64 + ty * 4];
            ulonglong2 b01 = *(const ulonglong2*)&Bs[k][tx * 4];
            ulonglong2 b23 = *(const ulonglong2*)&Bs[k][64 + tx * 4];

            unsigned long long av[8];
            av[0] = pack2(a0.x, a0.x); av[1] = pack2(a0.y, a0.y);
            av[2] = pack2(a0.z, a0.z); av[3] = pack2(a0.w, a0.w);
            av[4] = pack2(a1.x, a1.x); av[5] = pack2(a1.y, a1.y);
            av[6] = pack2(a1.z, a1.z); av[7] = pack2(a1.w, a1.w);

#pragma unroll
            for (int i = 0; i < 8; i++) {
                acc2[i][0] = ffma2(av[i], b01.x, acc2[i][0]);
                acc2[i][1] = ffma2(av[i], b01.y, acc2[i][1]);
                acc2[i][2] = ffma2(av[i], b23.x, acc2[i][2]);
                acc2[i][3] = ffma2(av[i], b23.y, acc2[i][3]);
            }
        }
        __syncthreads();
    }

#pragma unroll
    for (int i = 0; i < 8; i++) {
        int row = bm + ((i < 4) ? (ty * 4 + i) : (64 + ty * 4 + (i - 4)));
#pragma unroll
        for (int jj = 0; jj < 2; jj++) {
            int col = bn + jj * 64 + tx * 4;
            ulonglong2 bb = *(const ulonglong2*)&bias[col];
            ulonglong2 v;
            v.x = fadd2(acc2[i][jj * 2 + 0], bb.x);
            v.y = fadd2(acc2[i][jj * 2 + 1], bb.y);
            *(ulonglong2*)&g_xwx[(size_t)row * H_H + col] = v;
        }
    }
}

// ---------------------------------------------------------------------------
// Phase 2: cluster scan. 16 clusters x 8 CTAs. Cluster = 4 batch rows;
// CTA = 64-column Wh slice in SMEM. h exchanged via DSMEM (st.shared::cluster)
// + one cluster barrier per step. No global h traffic, no atomics.
// ---------------------------------------------------------------------------
#define SWH_F  (512 * 64)        // 32768 floats, sWh[k*64 + j]
#define SH_ROW 516               // padded h row (bank stagger)
#define SH_BUF (4 * SH_ROW)      // 2064 floats per buffer (4 rows)
#define SH_F   (2 * SH_BUF)      // double buffered
#define SRED_W 272               // 4*68 floats per warp-partial
#define SRED_F (8 * SRED_W)
#define SMEM_SCAN_BYTES ((SWH_F + SH_F + SRED_F) * 4)

__global__ __launch_bounds__(256, 1) __cluster_dims__(8, 1, 1)
void rnn_scan_kernel(const float* __restrict__ h0,
                     const float* __restrict__ Wh,
                     float* __restrict__ out)
{
    extern __shared__ float smem[];
    float* sWh  = smem;                 // [512][64]
    float* sH   = smem + SWH_F;         // [2][4][516]
    float* sRed = sH + SH_F;            // [8][4][68]

    const int tid  = threadIdx.x;
    const int rank = blockIdx.x & 7;    // column slice within cluster
    const int cid  = blockIdx.x >> 3;   // cluster -> batch group of 4 rows
    const int c0   = rank << 6;
    const int n0   = cid << 2;

    // Load Wh column slice once: sWh[k][j] = Wh[k][c0+j]
    for (int i = tid; i < 8192; i += 256) {
        int k = i >> 4, j4 = (i & 15) << 2;
        *(float4*)&sWh[k * 64 + j4] = *(const float4*)&Wh[(size_t)k * H_H + c0 + j4];
    }
    // Load h0 (this cluster's 4 rows, full 512) into buffer 0
    for (int i = tid; i < 512; i += 256) {
        int rr = i >> 7, q = (i & 127) << 2;
        *(float4*)&sH[rr * SH_ROW + q] = *(const float4*)&h0[(size_t)(n0 + rr) * H_H + q];
    }

    const int wid  = tid >> 5;          // warp owns k-range [wid*64, wid*64+64)
    const int lane = tid & 31;
    const int r_s  = lane & 3;          // batch row for slab
    const int line = lane >> 2;         // 0..7 -> cols line*4 and 32+line*4
    const int or_  = tid >> 6;          // owned output row
    const int oc_  = tid & 63;          // owned output col (within slice)

    unsigned int sh_u32;
    asm("{ .reg .u64 t; cvta.to.shared.u64 t, %1; cvt.u32.u64 %0, t; }"
        : "=r"(sh_u32) : "l"(sH));

    size_t oidx = (size_t)(n0 + or_) * T_T * H_H + c0 + oc_;
    float xv = __ldcg(&g_xwx[oidx]);    // xwx for t=0

    __syncthreads();

    const float* wbase = &sWh[(wid << 6) * 64 + (line << 2)];

    for (int t = 0; t < T_T; t++) {
        const int rb = t & 1, wb = rb ^ 1;

        // ---- slab: warp's 64-k contribution to 4 rows x 64 cols ----
        unsigned long long a0 = 0, a1 = 0, a2 = 0, a3 = 0;
        const float* hrow = &sH[rb * SH_BUF + r_s * SH_ROW + (wid << 6)];
#pragma unroll
        for (int kb = 0; kb < 16; kb++) {
            float4 h4 = *(const float4*)&hrow[kb << 2];
#pragma unroll
            for (int q = 0; q < 4; q++) {
                float hv = (q == 0) ? h4.x : (q == 1) ? h4.y : (q == 2) ? h4.z : h4.w;
                unsigned long long h2 = pack2(hv, hv);
                const float* wp = wbase + ((kb << 2) + q) * 64;
                ulonglong2 w0 = *(const ulonglong2*)wp;          // cols line*4..+3
                ulonglong2 w1 = *(const ulonglong2*)(wp + 32);   // cols 32+line*4..+3
                a0 = ffma2(h2, w0.x, a0);
                a1 = ffma2(h2, w0.y, a1);
                a2 = ffma2(h2, w1.x, a2);
                a3 = ffma2(h2, w1.y, a3);
            }
        }
        // ---- write warp partials ----
        {
            float* dst = &sRed[wid * SRED_W + r_s * 68 + (line << 2)];
            *(ulonglong2*)dst        = make_ulonglong2(a0, a1);
            *(ulonglong2*)(dst + 32) = make_ulonglong2(a2, a3);
        }
        __syncthreads();

        // ---- reduce 8 partials, activation, store ----
        float v = 0.f;
#pragma unroll
        for (int p = 0; p < 8; p++)
            v += sRed[p * SRED_W + or_ * 68 + oc_];
        v = tanhf(v + xv);
        out[oidx] = v;

        if (t < T_T - 1) {
            // ---- DSMEM broadcast of owned h value to all 8 cluster CTAs ----
            unsigned int loff = sh_u32 +
                (unsigned int)((wb * SH_BUF + or_ * SH_ROW + c0 + oc_) << 2);
#pragma unroll
            for (int pr = 0; pr < 8; pr++) {
                unsigned int ra;
                asm("mapa.shared::cluster.u32 %0, %1, %2;"
                    : "=r"(ra) : "r"(loff), "r"(pr));
                asm volatile("st.shared::cluster.f32 [%0], %1;"
                             :: "r"(ra), "f"(v) : "memory");
            }
            asm volatile("barrier.cluster.arrive.release.aligned;" ::: "memory");
            // hide xwx DRAM latency behind the cluster barrier
            oidx += H_H;
            xv = __ldcg(&g_xwx[oidx]);
            asm volatile("barrier.cluster.wait.acquire.aligned;" ::: "memory");
        }
    }
}

// ---------------------------------------------------------------------------
extern "C" void kernel_launch(void* const* d_in, const int* in_sizes, int n_in,
                              void* d_out, int out_size) {
    (void)in_sizes; (void)n_in; (void)out_size;
    const float* x  = (const float*)d_in[0];
    const float* h0 = (const float*)d_in[1];
    const float* Wx = (const float*)d_in[2];
    const float* Wh = (const float*)d_in[3];
    const float* b  = (const float*)d_in[4];
    float* out = (float*)d_out;

    dim3 g1(H_H / BN, (N_B * T_T) / BM);   // (4, 256)
    xwx_gemm_kernel<<<g1, 256>>>(x, Wx, b);

    cudaFuncSetAttribute((const void*)rnn_scan_kernel,
                         cudaFuncAttributeMaxDynamicSharedMemorySize,
                         SMEM_SCAN_BYTES);
    rnn_scan_kernel<<<128, 256, SMEM_SCAN_BYTES>>>(h0, Wh, out);
}